// round 1
// baseline (speedup 1.0000x reference)
#include <cuda_runtime.h>
#include <math.h>

#define NROW 4096
#define DIM  2048
#define LM   8
#define LD   128
#define LFSZ (LM * LD)   // 1024 floats per sample

// ---------------- scratch (device globals: no allocation allowed) ----------
__device__ float g_sq[NROW];
__device__ float g_dist[(size_t)NROW * NROW];   // 64 MB
__device__ int   g_tgt[NROW];
__device__ float g_dap[NROW];
__device__ float g_dan[NROW];
__device__ int   g_pind[NROW];
__device__ int   g_nind[NROW];
__device__ float g_ldap[NROW];
__device__ float g_ldan[NROW];

// ---------------- row squared norms ----------------------------------------
__global__ __launch_bounds__(256) void sq_kernel(const float* __restrict__ X) {
    int row = blockIdx.x;
    const float4* x4 = (const float4*)(X + (size_t)row * DIM);
    int t = threadIdx.x;
    float s = 0.f;
#pragma unroll
    for (int i = 0; i < DIM / 4 / 256; i++) {   // 2 iterations
        float4 v = x4[t + i * 256];
        s += v.x * v.x + v.y * v.y + v.z * v.z + v.w * v.w;
    }
#pragma unroll
    for (int o = 16; o > 0; o >>= 1) s += __shfl_down_sync(0xffffffffu, s, o);
    __shared__ float ws[8];
    if ((t & 31) == 0) ws[t >> 5] = s;
    __syncthreads();
    if (t < 8) {
        float v = ws[t];
#pragma unroll
        for (int o = 4; o > 0; o >>= 1) v += __shfl_down_sync(0xffu, v, o);
        if (t == 0) g_sq[row] = v;
    }
}

// ---------------- normalize targets (int32 vs int64 autodetect) ------------
__global__ void prep_targets(const int* __restrict__ t32) {
    // If the buffer actually holds little-endian int64 values in [0,1024),
    // every odd int32 word (the high half) is 0. Probability of a false
    // positive with real int32 data: (1/1024)^16 ~ 0.
    int flag = 0;
#pragma unroll
    for (int i = 1; i < 32; i += 2) flag |= t32[i];
    bool is64 = (flag == 0);
    int i = blockIdx.x * blockDim.x + threadIdx.x;
    if (i < NROW) {
        g_tgt[i] = is64 ? (int)(((const long long*)t32)[i]) : t32[i];
    }
}

// ---------------- Gram matrix -> dist, symmetric (upper triangle only) -----
// 128x128 block tile, BK=16, 256 threads, 8x8 micro-tile per thread.
__global__ __launch_bounds__(256, 2) void gemm_dist(const float* __restrict__ X) {
    int bi = blockIdx.y, bj = blockIdx.x;
    if (bj < bi) return;              // symmetry: only upper triangle

    __shared__ float As[16][128];
    __shared__ float Bs[16][128];

    int tid = threadIdx.x;
    int tx = tid & 15, ty = tid >> 4;
    int lr = tid >> 2;                // 0..63   load row
    int lc = (tid & 3) << 2;          // 0,4,8,12 load col (float4)

    const float* A = X + (size_t)(bi * 128 + lr) * DIM + lc;
    const float* B = X + (size_t)(bj * 128 + lr) * DIM + lc;

    float acc[8][8];
#pragma unroll
    for (int m = 0; m < 8; m++)
#pragma unroll
        for (int n = 0; n < 8; n++) acc[m][n] = 0.f;

    for (int k0 = 0; k0 < DIM; k0 += 16) {
        float4 a0 = *(const float4*)(A + k0);
        float4 a1 = *(const float4*)(A + (size_t)64 * DIM + k0);
        float4 b0 = *(const float4*)(B + k0);
        float4 b1 = *(const float4*)(B + (size_t)64 * DIM + k0);
        __syncthreads();
        As[lc + 0][lr] = a0.x; As[lc + 1][lr] = a0.y; As[lc + 2][lr] = a0.z; As[lc + 3][lr] = a0.w;
        As[lc + 0][lr + 64] = a1.x; As[lc + 1][lr + 64] = a1.y; As[lc + 2][lr + 64] = a1.z; As[lc + 3][lr + 64] = a1.w;
        Bs[lc + 0][lr] = b0.x; Bs[lc + 1][lr] = b0.y; Bs[lc + 2][lr] = b0.z; Bs[lc + 3][lr] = b0.w;
        Bs[lc + 0][lr + 64] = b1.x; Bs[lc + 1][lr + 64] = b1.y; Bs[lc + 2][lr + 64] = b1.z; Bs[lc + 3][lr + 64] = b1.w;
        __syncthreads();
#pragma unroll
        for (int k = 0; k < 16; k++) {
            float4 ra0 = *(const float4*)&As[k][ty * 8];
            float4 ra1 = *(const float4*)&As[k][ty * 8 + 4];
            float4 rb0 = *(const float4*)&Bs[k][tx * 8];
            float4 rb1 = *(const float4*)&Bs[k][tx * 8 + 4];
            float ra[8] = {ra0.x, ra0.y, ra0.z, ra0.w, ra1.x, ra1.y, ra1.z, ra1.w};
            float rb[8] = {rb0.x, rb0.y, rb0.z, rb0.w, rb1.x, rb1.y, rb1.z, rb1.w};
#pragma unroll
            for (int m = 0; m < 8; m++)
#pragma unroll
                for (int n = 0; n < 8; n++)
                    acc[m][n] = fmaf(ra[m], rb[n], acc[m][n]);
        }
    }

    // epilogue: d = sqrt(max(sq_i + sq_j - 2*g, 1e-12)), mirror for j<i
    float sqi[8], sqj[8];
#pragma unroll
    for (int m = 0; m < 8; m++) sqi[m] = g_sq[bi * 128 + ty * 8 + m];
#pragma unroll
    for (int n = 0; n < 8; n++) sqj[n] = g_sq[bj * 128 + tx * 8 + n];

#pragma unroll
    for (int m = 0; m < 8; m++) {
        int i = bi * 128 + ty * 8 + m;
#pragma unroll
        for (int n = 0; n < 8; n++) {
            int j = bj * 128 + tx * 8 + n;
            float d2 = sqi[m] + sqj[n] - 2.f * acc[m][n];
            float d = sqrtf(fmaxf(d2, 1e-12f));
            g_dist[(size_t)i * NROW + j] = d;
            if (bi != bj) g_dist[(size_t)j * NROW + i] = d;
        }
    }
}

// ---------------- hard example mining (one block per row) ------------------
__global__ __launch_bounds__(256) void mine_kernel() {
    int i = blockIdx.x;
    int ti = g_tgt[i];
    const float* row = g_dist + (size_t)i * NROW;
    int t = threadIdx.x;

    float bp = -1e30f; int bpi = NROW;
    float bn =  1e30f; int bni = NROW;
    for (int j = t; j < NROW; j += 256) {
        float d = row[j];
        if (g_tgt[j] == ti) {
            if (d > bp) { bp = d; bpi = j; }
        } else {
            if (d < bn) { bn = d; bni = j; }
        }
    }
    __shared__ float sp[256]; __shared__ int spi[256];
    __shared__ float sn[256]; __shared__ int sni[256];
    sp[t] = bp; spi[t] = bpi; sn[t] = bn; sni[t] = bni;
    __syncthreads();
    for (int o = 128; o > 0; o >>= 1) {
        if (t < o) {
            if (sp[t + o] > sp[t] || (sp[t + o] == sp[t] && spi[t + o] < spi[t])) {
                sp[t] = sp[t + o]; spi[t] = spi[t + o];
            }
            if (sn[t + o] < sn[t] || (sn[t + o] == sn[t] && sni[t + o] < sni[t])) {
                sn[t] = sn[t + o]; sni[t] = sni[t + o];
            }
        }
        __syncthreads();
    }
    if (t == 0) {
        g_dap[i] = sp[0]; g_pind[i] = spi[0];
        g_dan[i] = sn[0]; g_nind[i] = sni[0];
    }
}

// ---------------- local (aligned) distance: 8x8 DTW per sample -------------
// lf[n][m][d] = LF[n][d][m]  (LF is [N,128,8] row-major)
__global__ __launch_bounds__(64) void local_kernel(const float* __restrict__ LF) {
    int n = blockIdx.x;
    int other = (blockIdx.y == 0) ? g_pind[n] : g_nind[n];

    __shared__ float S[LFSZ];
    __shared__ float O[LFSZ];
    __shared__ float DM[64];

    int t = threadIdx.x;
    const float4* s4 = (const float4*)(LF + (size_t)n * LFSZ);
    const float4* o4 = (const float4*)(LF + (size_t)other * LFSZ);
    float4* S4 = (float4*)S; float4* O4 = (float4*)O;
    for (int i = t; i < LFSZ / 4; i += 64) { S4[i] = s4[i]; O4[i] = o4[i]; }
    __syncthreads();

    int m = t & 7, k = t >> 3;
    float ss = 0.f;
#pragma unroll 8
    for (int d = 0; d < LD; d++) {
        float diff = S[d * 8 + m] - O[d * 8 + k];
        ss = fmaf(diff, diff, ss);
    }
    float dist = sqrtf(fmaxf(ss, 1e-12f));
    // (e^d - 1)/(e^d + 1) == tanh(d/2)
    DM[m * 8 + k] = tanhf(0.5f * dist);
    __syncthreads();

    if (t == 0) {
        float r[8];
        r[0] = DM[0];
#pragma unroll
        for (int j = 1; j < 8; j++) r[j] = r[j - 1] + DM[j];
#pragma unroll
        for (int i2 = 1; i2 < 8; i2++) {
            float nr[8];
            nr[0] = r[0] + DM[i2 * 8];
#pragma unroll
            for (int j = 1; j < 8; j++)
                nr[j] = fminf(r[j], nr[j - 1]) + DM[i2 * 8 + j];
#pragma unroll
            for (int j = 0; j < 8; j++) r[j] = nr[j];
        }
        if (blockIdx.y == 0) g_ldap[n] = r[7];
        else                 g_ldan[n] = r[7];
    }
}

// ---------------- final reduction -------------------------------------------
__global__ __launch_bounds__(256) void final_kernel(float* __restrict__ out) {
    int t = threadIdx.x;
    float s1 = 0.f, s2 = 0.f;
    for (int i = t; i < NROW; i += 256) {
        s1 += fmaxf(g_dap[i]  - g_dan[i]  + 0.3f, 0.f);
        s2 += fmaxf(g_ldap[i] - g_ldan[i] + 0.3f, 0.f);
    }
#pragma unroll
    for (int o = 16; o > 0; o >>= 1) {
        s1 += __shfl_down_sync(0xffffffffu, s1, o);
        s2 += __shfl_down_sync(0xffffffffu, s2, o);
    }
    __shared__ float w1[8], w2[8];
    if ((t & 31) == 0) { w1[t >> 5] = s1; w2[t >> 5] = s2; }
    __syncthreads();
    if (t < 8) {
        float a = w1[t], b = w2[t];
#pragma unroll
        for (int o = 4; o > 0; o >>= 1) {
            a += __shfl_down_sync(0xffu, a, o);
            b += __shfl_down_sync(0xffu, b, o);
        }
        if (t == 0) {
            out[0] = a / (float)NROW;
            out[1] = b / (float)NROW;
        }
    }
}

// ---------------- launch -----------------------------------------------------
extern "C" void kernel_launch(void* const* d_in, const int* in_sizes, int n_in,
                              void* d_out, int out_size) {
    const float* X  = (const float*)d_in[0];       // [4096, 2048] fp32
    const int*   T  = (const int*)d_in[1];         // targets (int32 or int64, autodetected)
    const float* LF = (const float*)d_in[2];       // [4096, 128, 8] fp32
    float* out = (float*)d_out;

    sq_kernel<<<NROW, 256>>>(X);
    prep_targets<<<(NROW + 255) / 256, 256>>>(T);

    dim3 gg(NROW / 128, NROW / 128);               // 32 x 32, lower triangle exits
    gemm_dist<<<gg, 256>>>(X);

    mine_kernel<<<NROW, 256>>>();

    dim3 lg(NROW, 2);
    local_kernel<<<lg, 64>>>(LF);

    final_kernel<<<1, 256>>>(out);
}

// round 3
// speedup vs baseline: 3.6851x; 3.6851x over previous
#include <cuda_runtime.h>
#include <cstdint>
#include <math.h>

#define NROW 4096
#define DIM  2048
#define LM   8
#define LD   128
#define LFSZ (LM * LD)

// ---------------- GEMM tile config ----------------
#define BM 128
#define BN 128
#define BK 32
#define NCHUNK (DIM / BK)          // 64
#define STAGE_BYTES (2 * BM * BK * 4)   // A(16KB)+B(16KB) = 32768
#define OFF_SQ  67584                   // after 8x2112-float transpose buffers
#define DSMEM   (OFF_SQ + 1024)         // 68608

// ---------------- scratch ----------------
__device__ float g_sq[NROW];
__device__ float g_dist[(size_t)NROW * NROW];
__device__ int   g_tgt[NROW];
__device__ float g_dap[NROW];
__device__ float g_dan[NROW];
__device__ int   g_pind[NROW];
__device__ int   g_nind[NROW];
__device__ float g_ldap[NROW];
__device__ float g_ldan[NROW];

// ---------------- helpers ----------------
__device__ __forceinline__ uint32_t smem_u32(const void* p) {
    uint32_t a;
    asm("{ .reg .u64 t; cvta.to.shared.u64 t, %1; cvt.u32.u64 %0, t; }" : "=r"(a) : "l"(p));
    return a;
}
__device__ __forceinline__ void cp16(uint32_t dst, const void* src) {
    asm volatile("cp.async.cg.shared.global [%0], [%1], 16;" :: "r"(dst), "l"(src));
}
__device__ __forceinline__ void mma_tf32(float& c0, float& c1, float& c2, float& c3,
                                         uint32_t a0, uint32_t a1, uint32_t a2, uint32_t a3,
                                         uint32_t b0, uint32_t b1) {
    asm volatile(
        "mma.sync.aligned.m16n8k8.row.col.f32.tf32.tf32.f32 "
        "{%0,%1,%2,%3}, {%4,%5,%6,%7}, {%8,%9}, {%0,%1,%2,%3};"
        : "+f"(c0), "+f"(c1), "+f"(c2), "+f"(c3)
        : "r"(a0), "r"(a1), "r"(a2), "r"(a3), "r"(b0), "r"(b1));
}

// ---------------- row squared norms ----------------
__global__ __launch_bounds__(256) void sq_kernel(const float* __restrict__ X) {
    int row = blockIdx.x;
    const float4* x4 = (const float4*)(X + (size_t)row * DIM);
    int t = threadIdx.x;
    float s = 0.f;
#pragma unroll
    for (int i = 0; i < DIM / 4 / 256; i++) {
        float4 v = x4[t + i * 256];
        s += v.x * v.x + v.y * v.y + v.z * v.z + v.w * v.w;
    }
#pragma unroll
    for (int o = 16; o > 0; o >>= 1) s += __shfl_down_sync(0xffffffffu, s, o);
    __shared__ float ws[8];
    if ((t & 31) == 0) ws[t >> 5] = s;
    __syncthreads();
    if (t < 8) {
        float v = ws[t];
#pragma unroll
        for (int o = 4; o > 0; o >>= 1) v += __shfl_down_sync(0xffu, v, o);
        if (t == 0) g_sq[row] = v;
    }
}

// ---------------- targets normalize (int32/int64 autodetect) ----------------
__global__ void prep_targets(const int* __restrict__ t32) {
    int flag = 0;
#pragma unroll
    for (int i = 1; i < 32; i += 2) flag |= t32[i];
    bool is64 = (flag == 0);
    int i = blockIdx.x * blockDim.x + threadIdx.x;
    if (i < NROW) g_tgt[i] = is64 ? (int)(((const long long*)t32)[i]) : t32[i];
}

// ---------------- tf32 mma.sync Gram -> dist (upper triangle + mirror) ------
__global__ __launch_bounds__(256, 2) void gemm_dist_mma(const float* __restrict__ X) {
    extern __shared__ __align__(1024) char smem_raw[];
    uint32_t sbase = smem_u32(smem_raw);

    int tid = threadIdx.x, wid = tid >> 5, lane = tid & 31;
    int g = lane >> 2, tig = lane & 3;
    int wm = wid & 3, wn = wid >> 2;       // 4 warps in M (32 each), 2 in N (64 each)
    int m0 = wm * 32, n0 = wn * 64;

    // decode upper-triangle tile index: bi <= bj
    int t = blockIdx.x;
    int bj = 0;
    while ((bj + 1) * (bj + 2) / 2 <= t) bj++;
    int bi = t - bj * (bj + 1) / 2;

    float acc[2][8][4];
#pragma unroll
    for (int mi = 0; mi < 2; mi++)
#pragma unroll
        for (int ni = 0; ni < 8; ni++)
#pragma unroll
            for (int e = 0; e < 4; e++) acc[mi][ni][e] = 0.f;

    int lrow = tid >> 3;       // 0..31 base row within 32-row group
    int lcg  = tid & 7;        // 16B chunk within 128B row

    auto issue = [&](int chunk) {
        uint32_t base = sbase + (uint32_t)(chunk & 1) * STAGE_BYTES;
        const char* srcA = (const char*)(X + (size_t)(bi * BM) * DIM + chunk * BK) + lcg * 16;
        const char* srcB = (const char*)(X + (size_t)(bj * BN) * DIM + chunk * BK) + lcg * 16;
#pragma unroll
        for (int rr = 0; rr < 4; rr++) {
            int row = rr * 32 + lrow;
            uint32_t sw = ((uint32_t)(lcg * 16)) ^ ((uint32_t)(row & 7) * 16);
            cp16(base + row * 128 + sw, srcA + (size_t)row * (DIM * 4));
            cp16(base + 16384 + row * 128 + sw, srcB + (size_t)row * (DIM * 4));
        }
    };

    issue(0);
    asm volatile("cp.async.commit_group;" ::: "memory");
    issue(1);
    asm volatile("cp.async.commit_group;" ::: "memory");

    const uint32_t* smem_u = (const uint32_t*)smem_raw;

    for (int c = 0; c < NCHUNK; c++) {
        asm volatile("cp.async.wait_group 1;" ::: "memory");
        __syncthreads();
        const uint32_t* As = smem_u + (c & 1) * (STAGE_BYTES / 4);
        const uint32_t* Bs = As + 4096;
#pragma unroll
        for (int ks = 0; ks < 4; ks++) {
            int k0 = ks * 8;
            uint32_t a[2][4];
#pragma unroll
            for (int mi = 0; mi < 2; mi++) {
                int r0 = m0 + mi * 16 + g, r1 = r0 + 8;
                int s0 = (r0 & 7) << 2, s1 = (r1 & 7) << 2;
                a[mi][0] = As[r0 * 32 + ((k0 + tig) ^ s0)];
                a[mi][1] = As[r1 * 32 + ((k0 + tig) ^ s1)];
                a[mi][2] = As[r0 * 32 + ((k0 + tig + 4) ^ s0)];
                a[mi][3] = As[r1 * 32 + ((k0 + tig + 4) ^ s1)];
            }
            uint32_t b[8][2];
#pragma unroll
            for (int ni = 0; ni < 8; ni++) {
                int n = n0 + ni * 8 + g;
                int sn = (n & 7) << 2;
                b[ni][0] = Bs[n * 32 + ((k0 + tig) ^ sn)];
                b[ni][1] = Bs[n * 32 + ((k0 + tig + 4) ^ sn)];
            }
#pragma unroll
            for (int mi = 0; mi < 2; mi++)
#pragma unroll
                for (int ni = 0; ni < 8; ni++)
                    mma_tf32(acc[mi][ni][0], acc[mi][ni][1], acc[mi][ni][2], acc[mi][ni][3],
                             a[mi][0], a[mi][1], a[mi][2], a[mi][3],
                             b[ni][0], b[ni][1]);
        }
        __syncthreads();
        if (c + 2 < NCHUNK) issue(c + 2);
        asm volatile("cp.async.commit_group;" ::: "memory");
    }

    // ---- epilogue ----
    float* sqs = (float*)(smem_raw + OFF_SQ);
    if (tid < 128) {
        sqs[tid] = g_sq[bi * BM + tid];
        sqs[128 + tid] = g_sq[bj * BN + tid];
    }
    __syncthreads();

    bool diag = (bi == bj);
    float* tbw = (float*)smem_raw + wid * 2112;    // 64 x 33 per warp

    float dval[2][8][4];
#pragma unroll
    for (int mi = 0; mi < 2; mi++) {
        int rl0 = m0 + mi * 16 + g;
#pragma unroll
        for (int ni = 0; ni < 8; ni++) {
            int cl = n0 + ni * 8 + tig * 2;
#pragma unroll
            for (int e = 0; e < 4; e++) {
                int rl = rl0 + (e >> 1) * 8;
                int cc = cl + (e & 1);
                float d2 = sqs[rl] + sqs[128 + cc] - 2.f * acc[mi][ni][e];
                dval[mi][ni][e] = sqrtf(fmaxf(d2, 1e-12f));
            }
        }
    }

    // direct store (row-major, coalesced float2)
#pragma unroll
    for (int mi = 0; mi < 2; mi++) {
#pragma unroll
        for (int e2 = 0; e2 < 2; e2++) {
            int rl = m0 + mi * 16 + g + e2 * 8;
            size_t rowbase = (size_t)(bi * BM + rl) * NROW + bj * BN;
#pragma unroll
            for (int ni = 0; ni < 8; ni++) {
                int cl = n0 + ni * 8 + tig * 2;
                float2 v = make_float2(dval[mi][ni][e2 * 2], dval[mi][ni][e2 * 2 + 1]);
                *(float2*)(g_dist + rowbase + cl) = v;
            }
        }
    }

    // mirror store via per-warp SMEM transpose (skip on diagonal tiles:
    // the full 128x128 tile already contains both triangles)
    if (!diag) {
#pragma unroll
        for (int mi = 0; mi < 2; mi++)
#pragma unroll
            for (int ni = 0; ni < 8; ni++)
#pragma unroll
                for (int e = 0; e < 4; e++) {
                    int ml = mi * 16 + g + (e >> 1) * 8;            // 0..31 within warp
                    int nl = ni * 8 + tig * 2 + (e & 1);            // 0..63 within warp
                    tbw[nl * 33 + ml] = dval[mi][ni][e];
                }
        __syncwarp();
        size_t colbase = (size_t)bi * BM + m0 + lane;
        for (int jl = 0; jl < 64; jl++) {
            int j = bj * BN + n0 + jl;
            g_dist[(size_t)j * NROW + colbase] = tbw[jl * 33 + lane];
        }
    }
}

// ---------------- hard example mining (float4/int4) ----------------
__global__ __launch_bounds__(256) void mine_kernel() {
    int i = blockIdx.x;
    int ti = g_tgt[i];
    const float4* row4 = (const float4*)(g_dist + (size_t)i * NROW);
    const int4* tg4 = (const int4*)g_tgt;
    int t = threadIdx.x;
    float bp = -1e30f; int bpi = 0;
    float bn = 1e30f;  int bni = 0;
#pragma unroll 2
    for (int j4 = t; j4 < NROW / 4; j4 += 256) {
        float4 d = row4[j4];
        int4 tg = tg4[j4];
        int jb = j4 * 4;
        if (tg.x == ti) { if (d.x > bp) { bp = d.x; bpi = jb; } }     else { if (d.x < bn) { bn = d.x; bni = jb; } }
        if (tg.y == ti) { if (d.y > bp) { bp = d.y; bpi = jb + 1; } } else { if (d.y < bn) { bn = d.y; bni = jb + 1; } }
        if (tg.z == ti) { if (d.z > bp) { bp = d.z; bpi = jb + 2; } } else { if (d.z < bn) { bn = d.z; bni = jb + 2; } }
        if (tg.w == ti) { if (d.w > bp) { bp = d.w; bpi = jb + 3; } } else { if (d.w < bn) { bn = d.w; bni = jb + 3; } }
    }
    __shared__ float sp[256]; __shared__ int spi[256];
    __shared__ float sn[256]; __shared__ int sni[256];
    sp[t] = bp; spi[t] = bpi; sn[t] = bn; sni[t] = bni;
    __syncthreads();
    for (int o = 128; o > 0; o >>= 1) {
        if (t < o) {
            if (sp[t + o] > sp[t] || (sp[t + o] == sp[t] && spi[t + o] < spi[t])) {
                sp[t] = sp[t + o]; spi[t] = spi[t + o];
            }
            if (sn[t + o] < sn[t] || (sn[t + o] == sn[t] && sni[t + o] < sni[t])) {
                sn[t] = sn[t + o]; sni[t] = sni[t + o];
            }
        }
        __syncthreads();
    }
    if (t == 0) {
        g_dap[i] = sp[0]; g_pind[i] = spi[0];
        g_dan[i] = sn[0]; g_nind[i] = sni[0];
    }
}

// ---------------- local (aligned) distance: 8x8 DTW per sample ----------------
__global__ __launch_bounds__(64) void local_kernel(const float* __restrict__ LF) {
    int n = blockIdx.x;
    int other = (blockIdx.y == 0) ? g_pind[n] : g_nind[n];

    __shared__ float S[LFSZ];
    __shared__ float O[LFSZ];
    __shared__ float DM[64];

    int t = threadIdx.x;
    const float4* s4 = (const float4*)(LF + (size_t)n * LFSZ);
    const float4* o4 = (const float4*)(LF + (size_t)other * LFSZ);
    float4* S4 = (float4*)S; float4* O4 = (float4*)O;
    for (int i = t; i < LFSZ / 4; i += 64) { S4[i] = s4[i]; O4[i] = o4[i]; }
    __syncthreads();

    int m = t & 7, k = t >> 3;
    float ss = 0.f;
#pragma unroll 8
    for (int d = 0; d < LD; d++) {
        float diff = S[d * 8 + m] - O[d * 8 + k];
        ss = fmaf(diff, diff, ss);
    }
    float dist = sqrtf(fmaxf(ss, 1e-12f));
    DM[m * 8 + k] = tanhf(0.5f * dist);
    __syncthreads();

    if (t == 0) {
        float r[8];
        r[0] = DM[0];
#pragma unroll
        for (int j = 1; j < 8; j++) r[j] = r[j - 1] + DM[j];
#pragma unroll
        for (int i2 = 1; i2 < 8; i2++) {
            float nr[8];
            nr[0] = r[0] + DM[i2 * 8];
#pragma unroll
            for (int j = 1; j < 8; j++)
                nr[j] = fminf(r[j], nr[j - 1]) + DM[i2 * 8 + j];
#pragma unroll
            for (int j = 0; j < 8; j++) r[j] = nr[j];
        }
        if (blockIdx.y == 0) g_ldap[n] = r[7];
        else                 g_ldan[n] = r[7];
    }
}

// ---------------- final reduction ----------------
__global__ __launch_bounds__(256) void final_kernel(float* __restrict__ out) {
    int t = threadIdx.x;
    float s1 = 0.f, s2 = 0.f;
    for (int i = t; i < NROW; i += 256) {
        s1 += fmaxf(g_dap[i]  - g_dan[i]  + 0.3f, 0.f);
        s2 += fmaxf(g_ldap[i] - g_ldan[i] + 0.3f, 0.f);
    }
#pragma unroll
    for (int o = 16; o > 0; o >>= 1) {
        s1 += __shfl_down_sync(0xffffffffu, s1, o);
        s2 += __shfl_down_sync(0xffffffffu, s2, o);
    }
    __shared__ float w1[8], w2[8];
    if ((t & 31) == 0) { w1[t >> 5] = s1; w2[t >> 5] = s2; }
    __syncthreads();
    if (t < 8) {
        float a = w1[t], b = w2[t];
#pragma unroll
        for (int o = 4; o > 0; o >>= 1) {
            a += __shfl_down_sync(0xffu, a, o);
            b += __shfl_down_sync(0xffu, b, o);
        }
        if (t == 0) {
            out[0] = a / (float)NROW;
            out[1] = b / (float)NROW;
        }
    }
}

// ---------------- launch ----------------
extern "C" void kernel_launch(void* const* d_in, const int* in_sizes, int n_in,
                              void* d_out, int out_size) {
    const float* X  = (const float*)d_in[0];
    const int*   T  = (const int*)d_in[1];
    const float* LF = (const float*)d_in[2];
    float* out = (float*)d_out;

    cudaFuncSetAttribute(gemm_dist_mma, cudaFuncAttributeMaxDynamicSharedMemorySize, DSMEM);

    sq_kernel<<<NROW, 256>>>(X);
    prep_targets<<<(NROW + 255) / 256, 256>>>(T);
    gemm_dist_mma<<<528, 256, DSMEM>>>(X);
    mine_kernel<<<NROW, 256>>>();
    dim3 lg(NROW, 2);
    local_kernel<<<lg, 64>>>(LF);
    final_kernel<<<1, 256>>>(out);
}

// round 4
// speedup vs baseline: 3.9632x; 1.0754x over previous
#include <cuda_runtime.h>
#include <cstdint>
#include <math.h>

#define NROW 4096
#define DIM  2048
#define LM   8
#define LD   128
#define LFSZ (LM * LD)

// ---------------- GEMM tile config ----------------
#define BM 128
#define BN 128
#define BK 32
#define NCHUNK (DIM / BK)               // 64
#define STAGE_BYTES (2 * BM * BK * 4)   // 32768
#define DSMEM (2 * STAGE_BYTES)         // 65536

typedef unsigned long long ull;

// ---------------- scratch ----------------
__device__ float g_sq[NROW];
__device__ int   g_tgt[NROW];
__device__ ull   g_posP[NROW];
__device__ ull   g_negP[NROW];
__device__ float g_dap[NROW];
__device__ float g_dan[NROW];
__device__ int   g_pind[NROW];
__device__ int   g_nind[NROW];
__device__ float g_ldap[NROW];
__device__ float g_ldan[NROW];

// ---------------- helpers ----------------
__device__ __forceinline__ uint32_t smem_u32(const void* p) {
    uint32_t a;
    asm("{ .reg .u64 t; cvta.to.shared.u64 t, %1; cvt.u32.u64 %0, t; }" : "=r"(a) : "l"(p));
    return a;
}
__device__ __forceinline__ void cp16(uint32_t dst, const void* src) {
    asm volatile("cp.async.cg.shared.global [%0], [%1], 16;" :: "r"(dst), "l"(src));
}
__device__ __forceinline__ void mma_tf32(float& c0, float& c1, float& c2, float& c3,
                                         uint32_t a0, uint32_t a1, uint32_t a2, uint32_t a3,
                                         uint32_t b0, uint32_t b1) {
    asm volatile(
        "mma.sync.aligned.m16n8k8.row.col.f32.tf32.tf32.f32 "
        "{%0,%1,%2,%3}, {%4,%5,%6,%7}, {%8,%9}, {%0,%1,%2,%3};"
        : "+f"(c0), "+f"(c1), "+f"(c2), "+f"(c3)
        : "r"(a0), "r"(a1), "r"(a2), "r"(a3), "r"(b0), "r"(b1));
}

// ---------------- row squared norms ----------------
__global__ __launch_bounds__(256) void sq_kernel(const float* __restrict__ X) {
    int row = blockIdx.x;
    const float4* x4 = (const float4*)(X + (size_t)row * DIM);
    int t = threadIdx.x;
    float s = 0.f;
#pragma unroll
    for (int i = 0; i < DIM / 4 / 256; i++) {
        float4 v = x4[t + i * 256];
        s += v.x * v.x + v.y * v.y + v.z * v.z + v.w * v.w;
    }
#pragma unroll
    for (int o = 16; o > 0; o >>= 1) s += __shfl_down_sync(0xffffffffu, s, o);
    __shared__ float ws[8];
    if ((t & 31) == 0) ws[t >> 5] = s;
    __syncthreads();
    if (t < 8) {
        float v = ws[t];
#pragma unroll
        for (int o = 4; o > 0; o >>= 1) v += __shfl_down_sync(0xffu, v, o);
        if (t == 0) g_sq[row] = v;
    }
}

// ------------- targets normalize + packed-mining init -------------
__global__ void prep_targets(const int* __restrict__ t32) {
    int flag = 0;
#pragma unroll
    for (int i = 1; i < 32; i += 2) flag |= t32[i];
    bool is64 = (flag == 0);
    int i = blockIdx.x * blockDim.x + threadIdx.x;
    if (i < NROW) {
        g_tgt[i] = is64 ? (int)(((const long long*)t32)[i]) : t32[i];
        g_posP[i] = 0ull;
        g_negP[i] = ~0ull;
    }
}

// ------- tf32 mma.sync Gram + FUSED hard-example mining (no dist array) ------
__global__ __launch_bounds__(256, 2) void gemm_mine(const float* __restrict__ X) {
    extern __shared__ __align__(1024) char smem_raw[];
    uint32_t sbase = smem_u32(smem_raw);

    int tid = threadIdx.x, wid = tid >> 5, lane = tid & 31;
    int g = lane >> 2, tig = lane & 3;
    int wm = wid & 3, wn = wid >> 2;     // 4 warps in M (32 rows), 2 in N (64 cols)
    int m0 = wm * 32, n0 = wn * 64;

    // upper-triangle tile index: bi <= bj
    int t = blockIdx.x;
    int bj = 0;
    while ((bj + 1) * (bj + 2) / 2 <= t) bj++;
    int bi = t - bj * (bj + 1) / 2;

    float acc[2][8][4];
#pragma unroll
    for (int mi = 0; mi < 2; mi++)
#pragma unroll
        for (int ni = 0; ni < 8; ni++)
#pragma unroll
            for (int e = 0; e < 4; e++) acc[mi][ni][e] = 0.f;

    int lrow = tid >> 3;
    int lcg  = tid & 7;

    auto issue = [&](int chunk) {
        uint32_t base = sbase + (uint32_t)(chunk & 1) * STAGE_BYTES;
        const char* srcA = (const char*)(X + (size_t)(bi * BM) * DIM + chunk * BK) + lcg * 16;
        const char* srcB = (const char*)(X + (size_t)(bj * BN) * DIM + chunk * BK) + lcg * 16;
#pragma unroll
        for (int rr = 0; rr < 4; rr++) {
            int row = rr * 32 + lrow;
            uint32_t sw = ((uint32_t)(lcg * 16)) ^ ((uint32_t)(row & 7) * 16);
            cp16(base + row * 128 + sw, srcA + (size_t)row * (DIM * 4));
            cp16(base + 16384 + row * 128 + sw, srcB + (size_t)row * (DIM * 4));
        }
    };

    issue(0);
    asm volatile("cp.async.commit_group;" ::: "memory");
    issue(1);
    asm volatile("cp.async.commit_group;" ::: "memory");

    const uint32_t* smem_u = (const uint32_t*)smem_raw;

    for (int c = 0; c < NCHUNK; c++) {
        asm volatile("cp.async.wait_group 1;" ::: "memory");
        __syncthreads();
        const uint32_t* As = smem_u + (c & 1) * (STAGE_BYTES / 4);
        const uint32_t* Bs = As + 4096;
#pragma unroll
        for (int ks = 0; ks < 4; ks++) {
            int k0 = ks * 8;
            uint32_t a[2][4];
#pragma unroll
            for (int mi = 0; mi < 2; mi++) {
                int r0 = m0 + mi * 16 + g, r1 = r0 + 8;
                int s0 = (r0 & 7) << 2, s1 = (r1 & 7) << 2;
                a[mi][0] = As[r0 * 32 + ((k0 + tig) ^ s0)];
                a[mi][1] = As[r1 * 32 + ((k0 + tig) ^ s1)];
                a[mi][2] = As[r0 * 32 + ((k0 + tig + 4) ^ s0)];
                a[mi][3] = As[r1 * 32 + ((k0 + tig + 4) ^ s1)];
            }
            uint32_t b[8][2];
#pragma unroll
            for (int ni = 0; ni < 8; ni++) {
                int n = n0 + ni * 8 + g;
                int sn = (n & 7) << 2;
                b[ni][0] = Bs[n * 32 + ((k0 + tig) ^ sn)];
                b[ni][1] = Bs[n * 32 + ((k0 + tig + 4) ^ sn)];
            }
#pragma unroll
            for (int mi = 0; mi < 2; mi++)
#pragma unroll
                for (int ni = 0; ni < 8; ni++)
                    mma_tf32(acc[mi][ni][0], acc[mi][ni][1], acc[mi][ni][2], acc[mi][ni][3],
                             a[mi][0], a[mi][1], a[mi][2], a[mi][3],
                             b[ni][0], b[ni][1]);
        }
        __syncthreads();
        if (c + 2 < NCHUNK) issue(c + 2);
        asm volatile("cp.async.commit_group;" ::: "memory");
    }

    // ---- epilogue: dist + fused mining (reuse stage smem, safe after sync) ----
    float* sqs = (float*)smem_raw;                 // 256 floats
    int* tr = (int*)(smem_raw + 1024);             // 128 ints
    int* tc = tr + 128;
    if (tid < 128) {
        sqs[tid]       = g_sq[bi * BM + tid];
        sqs[128 + tid] = g_sq[bj * BN + tid];
        tr[tid] = g_tgt[bi * BM + tid];
        tc[tid] = g_tgt[bj * BN + tid];
    }
    __syncthreads();

    float dval[2][8][4];
#pragma unroll
    for (int mi = 0; mi < 2; mi++) {
#pragma unroll
        for (int ni = 0; ni < 8; ni++) {
#pragma unroll
            for (int e = 0; e < 4; e++) {
                int rl = m0 + mi * 16 + g + (e >> 1) * 8;
                int cl = n0 + ni * 8 + tig * 2 + (e & 1);
                float d2 = sqs[rl] + sqs[128 + cl] - 2.f * acc[mi][ni][e];
                dval[mi][ni][e] = sqrtf(fmaxf(d2, 1e-12f));
            }
        }
    }

    bool diag = (bi == bj);

    // ---- row-direction mining: rows bi*BM + rl, cols bj*BN + cl ----
#pragma unroll
    for (int mi = 0; mi < 2; mi++) {
#pragma unroll
        for (int e2 = 0; e2 < 2; e2++) {
            int rl = m0 + mi * 16 + g + e2 * 8;
            int ti = tr[rl];
            ull pp = 0ull, nn = ~0ull;
#pragma unroll
            for (int ni = 0; ni < 8; ni++) {
#pragma unroll
                for (int e1 = 0; e1 < 2; e1++) {
                    int cl = n0 + ni * 8 + tig * 2 + e1;
                    float d = dval[mi][ni][e2 * 2 + e1];
                    unsigned j = (unsigned)(bj * BN + cl);
                    ull fb = ((ull)__float_as_uint(d)) << 32;
                    if (tc[cl] == ti) { ull cnd = fb | (0xFFFFFFFFu - j); pp = pp > cnd ? pp : cnd; }
                    else              { ull cnd = fb | j;                  nn = nn < cnd ? nn : cnd; }
                }
            }
#pragma unroll
            for (int off = 1; off <= 2; off <<= 1) {
                ull o1 = __shfl_xor_sync(0xffffffffu, pp, off);
                ull o2 = __shfl_xor_sync(0xffffffffu, nn, off);
                pp = pp > o1 ? pp : o1;
                nn = nn < o2 ? nn : o2;
            }
            if (tig == 0) {
                atomicMax(&g_posP[bi * BM + rl], pp);
                atomicMin(&g_negP[bi * BM + rl], nn);
            }
        }
    }

    // ---- col-direction mining (mirror): rows bj*BN + cl, cols bi*BM + rl ----
    if (!diag) {
#pragma unroll
        for (int ni = 0; ni < 8; ni++) {
#pragma unroll
            for (int e1 = 0; e1 < 2; e1++) {
                int cl = n0 + ni * 8 + tig * 2 + e1;
                int tj = tc[cl];
                ull pp = 0ull, nn = ~0ull;
#pragma unroll
                for (int mi = 0; mi < 2; mi++) {
#pragma unroll
                    for (int e2 = 0; e2 < 2; e2++) {
                        int rl = m0 + mi * 16 + g + e2 * 8;
                        float d = dval[mi][ni][e2 * 2 + e1];
                        unsigned i = (unsigned)(bi * BM + rl);
                        ull fb = ((ull)__float_as_uint(d)) << 32;
                        if (tr[rl] == tj) { ull cnd = fb | (0xFFFFFFFFu - i); pp = pp > cnd ? pp : cnd; }
                        else              { ull cnd = fb | i;                  nn = nn < cnd ? nn : cnd; }
                    }
                }
#pragma unroll
                for (int off = 4; off <= 16; off <<= 1) {
                    ull o1 = __shfl_xor_sync(0xffffffffu, pp, off);
                    ull o2 = __shfl_xor_sync(0xffffffffu, nn, off);
                    pp = pp > o1 ? pp : o1;
                    nn = nn < o2 ? nn : o2;
                }
                if (g == 0) {
                    atomicMax(&g_posP[bj * BN + cl], pp);
                    atomicMin(&g_negP[bj * BN + cl], nn);
                }
            }
        }
    }
}

// ---------------- unpack mining results ----------------
__global__ void finalize_mine() {
    int i = blockIdx.x * blockDim.x + threadIdx.x;
    if (i < NROW) {
        ull p = g_posP[i];
        ull n = g_negP[i];
        g_dap[i] = __uint_as_float((unsigned)(p >> 32));
        g_pind[i] = (int)(0xFFFFFFFFu - (unsigned)p);
        g_dan[i] = __uint_as_float((unsigned)(n >> 32));
        g_nind[i] = (int)(unsigned)n;
    }
}

// -------- local (aligned) distance: pos+neg fused, one block per sample ------
__global__ __launch_bounds__(128) void local_kernel(const float* __restrict__ LF) {
    int n = blockIdx.x;
    __shared__ float S[LFSZ];
    __shared__ float P[LFSZ];
    __shared__ float Q[LFSZ];
    __shared__ float DMp[64];
    __shared__ float DMn[64];

    int t = threadIdx.x;
    int pi = g_pind[n], nix = g_nind[n];
    const float4* s4 = (const float4*)(LF + (size_t)n * LFSZ);
    const float4* p4 = (const float4*)(LF + (size_t)pi * LFSZ);
    const float4* q4 = (const float4*)(LF + (size_t)nix * LFSZ);
    float4* S4 = (float4*)S; float4* P4 = (float4*)P; float4* Q4 = (float4*)Q;
    for (int i = t; i < LFSZ / 4; i += 128) { S4[i] = s4[i]; P4[i] = p4[i]; Q4[i] = q4[i]; }
    __syncthreads();

    int half = t >> 6, tt = t & 63;
    int m = tt & 7, k = tt >> 3;
    const float* O = half ? Q : P;
    float ss = 0.f;
#pragma unroll 8
    for (int d = 0; d < LD; d++) {
        float diff = S[d * 8 + m] - O[d * 8 + k];
        ss = fmaf(diff, diff, ss);
    }
    float dist = sqrtf(fmaxf(ss, 1e-12f));
    float v = tanhf(0.5f * dist);
    if (half) DMn[m * 8 + k] = v; else DMp[m * 8 + k] = v;
    __syncthreads();

    if (tt == 0) {
        const float* DM = half ? DMn : DMp;
        float r[8];
        r[0] = DM[0];
#pragma unroll
        for (int j = 1; j < 8; j++) r[j] = r[j - 1] + DM[j];
#pragma unroll
        for (int i2 = 1; i2 < 8; i2++) {
            float nr[8];
            nr[0] = r[0] + DM[i2 * 8];
#pragma unroll
            for (int j = 1; j < 8; j++)
                nr[j] = fminf(r[j], nr[j - 1]) + DM[i2 * 8 + j];
#pragma unroll
            for (int j = 0; j < 8; j++) r[j] = nr[j];
        }
        if (half) g_ldan[n] = r[7]; else g_ldap[n] = r[7];
    }
}

// ---------------- final reduction ----------------
__global__ __launch_bounds__(256) void final_kernel(float* __restrict__ out) {
    int t = threadIdx.x;
    float s1 = 0.f, s2 = 0.f;
    for (int i = t; i < NROW; i += 256) {
        s1 += fmaxf(g_dap[i]  - g_dan[i]  + 0.3f, 0.f);
        s2 += fmaxf(g_ldap[i] - g_ldan[i] + 0.3f, 0.f);
    }
#pragma unroll
    for (int o = 16; o > 0; o >>= 1) {
        s1 += __shfl_down_sync(0xffffffffu, s1, o);
        s2 += __shfl_down_sync(0xffffffffu, s2, o);
    }
    __shared__ float w1[8], w2[8];
    if ((t & 31) == 0) { w1[t >> 5] = s1; w2[t >> 5] = s2; }
    __syncthreads();
    if (t < 8) {
        float a = w1[t], b = w2[t];
#pragma unroll
        for (int o = 4; o > 0; o >>= 1) {
            a += __shfl_down_sync(0xffu, a, o);
            b += __shfl_down_sync(0xffu, b, o);
        }
        if (t == 0) {
            out[0] = a / (float)NROW;
            out[1] = b / (float)NROW;
        }
    }
}

// ---------------- launch ----------------
extern "C" void kernel_launch(void* const* d_in, const int* in_sizes, int n_in,
                              void* d_out, int out_size) {
    const float* X  = (const float*)d_in[0];
    const int*   T  = (const int*)d_in[1];
    const float* LF = (const float*)d_in[2];
    float* out = (float*)d_out;

    cudaFuncSetAttribute(gemm_mine, cudaFuncAttributeMaxDynamicSharedMemorySize, DSMEM);

    sq_kernel<<<NROW, 256>>>(X);
    prep_targets<<<(NROW + 255) / 256, 256>>>(T);
    gemm_mine<<<528, 256, DSMEM>>>(X);
    finalize_mine<<<(NROW + 255) / 256, 256>>>();
    local_kernel<<<NROW, 128>>>(LF);
    final_kernel<<<1, 256>>>(out);
}